// round 14
// baseline (speedup 1.0000x reference)
#include <cuda_runtime.h>
#include <cstdint>

#define NB 128
#define NT 256
#define Bq 32
#define Tq 256
#define Dq 512
#define Lq 128
#define K4 2048

// ------------- device scratch (static globals: allowed) ---------------------
__device__ float g_xW[Bq * Tq * K4];        // 64 MB  x@W + b
__device__ float g_attctx[Bq * Lq * Dq];    // 8 MB   ctx@W_ctx_att + b_att
__device__ float g_UVpT[K4 * 1024];         // 8 MB   [U;V] transposed -> [k][d]
__device__ float g_WhT[Dq * Dq];            // 1 MB   W_h_att transposed -> [a][d]
__device__ float g_zT[2][1024 * Bq];        // ping-pong z = [h;wctx], [d][b]
__device__ float g_c[Dq * Bq];              // cell state [j][b]
__device__ float g_hatt[Bq * Dq];
__device__ float g_prj[Bq * Lq];
__device__ unsigned long long g_barcnt;

// ------------- math ----------------------------------------------------------
__device__ __forceinline__ float sigmoid_f(float x) {
    return __fdividef(1.0f, 1.0f + __expf(-x));
}
__device__ __forceinline__ float tanh_f(float x) {
    float e = __expf(2.0f * x);
    return 1.0f - __fdividef(2.0f, e + 1.0f);
}

// ------------- grid barrier (monotonic counter) ------------------------------
__device__ __forceinline__ void grid_barrier(unsigned long long target) {
    __syncthreads();
    if (threadIdx.x == 0) {
        __threadfence();
        atomicAdd(&g_barcnt, 1ULL);
        volatile unsigned long long* c = &g_barcnt;
        while (*c < target) { __nanosleep(64); }
        __threadfence();
    }
    __syncthreads();
}

// ------------- init: transposes + state zero ---------------------------------
__global__ void k_init(const float* __restrict__ U, const float* __restrict__ V,
                       const float* __restrict__ Wh) {
    int tid = blockIdx.x * blockDim.x + threadIdx.x;
    int n = blockDim.x * gridDim.x;
    if (tid == 0) g_barcnt = 0ULL;
    for (int i = tid; i < 2 * 1024 * Bq; i += n) g_zT[0][i] = 0.0f;   // both bufs
    for (int i = tid; i < Dq * Bq; i += n) g_c[i] = 0.0f;
    for (int i = tid; i < Dq * Dq; i += n) {
        int a = i >> 9, d = i & 511;
        g_WhT[i] = Wh[d * Dq + a];
    }
    for (int i = tid; i < K4 * 1024; i += n) {
        int k = i >> 10, d = i & 1023;
        g_UVpT[i] = (d < Dq) ? U[(size_t)d * K4 + k] : V[(size_t)(d - Dq) * K4 + k];
    }
}

// ------------- 128x128x16 tiled SGEMM: C = A*B + bias ------------------------
__device__ __forceinline__ void gemm128_body(
    const float* __restrict__ A, const float* __restrict__ Bm,
    const float* __restrict__ bias, float* __restrict__ C,
    int M, int N, int K, float* As, float* Bs)
{
    const int tid = threadIdx.x;
    const int m0 = blockIdx.y * 128, n0 = blockIdx.x * 128;
    const int ty = tid >> 4, tx = tid & 15;
    const int arow = tid >> 2, acg = tid & 3;
    const int brow = tid >> 5, bcol = (tid & 31) * 4;

    float acc[8][8];
#pragma unroll
    for (int i = 0; i < 8; i++)
#pragma unroll
        for (int j = 0; j < 8; j++) acc[i][j] = 0.0f;

    for (int k0 = 0; k0 < K; k0 += 16) {
#pragma unroll
        for (int it = 0; it < 2; it++) {
            int r = arow + it * 64;
            float4 a4 = *(const float4*)&A[(size_t)(m0 + r) * K + k0 + acg * 4];
            As[(acg * 4 + 0) * 128 + r] = a4.x;
            As[(acg * 4 + 1) * 128 + r] = a4.y;
            As[(acg * 4 + 2) * 128 + r] = a4.z;
            As[(acg * 4 + 3) * 128 + r] = a4.w;
        }
#pragma unroll
        for (int it = 0; it < 2; it++) {
            int r = brow + it * 8;
            *(float4*)&Bs[r * 128 + bcol] =
                *(const float4*)&Bm[(size_t)(k0 + r) * N + n0 + bcol];
        }
        __syncthreads();
#pragma unroll
        for (int kk = 0; kk < 16; kk++) {
            float ar[8], br[8];
            *(float4*)&ar[0] = *(const float4*)&As[kk * 128 + ty * 8];
            *(float4*)&ar[4] = *(const float4*)&As[kk * 128 + ty * 8 + 4];
            *(float4*)&br[0] = *(const float4*)&Bs[kk * 128 + tx * 8];
            *(float4*)&br[4] = *(const float4*)&Bs[kk * 128 + tx * 8 + 4];
#pragma unroll
            for (int i = 0; i < 8; i++)
#pragma unroll
                for (int j = 0; j < 8; j++)
                    acc[i][j] = fmaf(ar[i], br[j], acc[i][j]);
        }
        __syncthreads();
    }
#pragma unroll
    for (int i = 0; i < 8; i++) {
        int row = m0 + ty * 8 + i;
#pragma unroll
        for (int j = 0; j < 8; j++) {
            int col = n0 + tx * 8 + j;
            C[(size_t)row * N + col] = acc[i][j] + bias[col];
        }
    }
}

__global__ void __launch_bounds__(256) k_gemm_xw(
    const float* __restrict__ x, const float* __restrict__ W,
    const float* __restrict__ b) {
    __shared__ __align__(16) float As[16 * 128];
    __shared__ __align__(16) float Bs[16 * 128];
    gemm128_body(x, W, b, g_xW, Bq * Tq, K4, Dq, As, Bs);
}
__global__ void __launch_bounds__(256) k_gemm_attctx(
    const float* __restrict__ ctx, const float* __restrict__ Wc,
    const float* __restrict__ ba) {
    __shared__ __align__(16) float As[16 * 128];
    __shared__ __align__(16) float Bs[16 * 128];
    gemm128_body(ctx, Wc, ba, g_attctx, Bq * Lq, Dq, Dq, As, Bs);
}

// ------------- persistent recurrence -----------------------------------------
extern __shared__ float dynsm[];   // 64 KB: zT staging

__global__ void __launch_bounds__(NT, 1) k_recur(
    const float* __restrict__ ctx,      // (B, L, D)
    const float* __restrict__ wprj,     // (A_HID,)
    float* __restrict__ out)            // (B, T, D)
{
    __shared__ float s_ps[1024];
    __shared__ float s_pre[512];
    __shared__ float s_hs[512];
    __shared__ float s_ws[512];
    __shared__ float s_al[128];
    __shared__ float s_red[128];

    const int tid = threadIdx.x;
    const int blk = blockIdx.x;
    unsigned long long bt = 0;

    // persistent thread coords
    // phase A: a-tile of 4, all b, 2-way ksplit
    const int aA = tid & 3;
    const int bA = (tid >> 2) & 31;
    const int khA = tid >> 7;                 // 0/1 -> 256 d each
    const int abase = blk * 4;
    // phase B: b = blk>>2, 32 l, 8-way a-split
    const int bb = blk >> 2;
    const int lg = (blk & 3) * 32;
    const int lloc = tid >> 3;                // 0..31
    const int ach = tid & 7;                  // 64 a each
    // phase C
    const int cg = (blk & 3) * 128;
    // phase D: column tile = 4 j x 4 gates
    const int jt = blk;                       // 0..127 -> j base jt*4
    const int cD = tid & 15;                  // 16 cols
    const int rD = tid >> 4;
    const int b0 = (rD & 7) * 4;              // 4 b per thread
    const int khD = rD >> 3;                  // 0/1
    const int gD = cD >> 2, jjD = cD & 3;
    const int kcol = gD * 512 + jt * 4 + jjD;
    const float* wrow = &g_UVpT[(size_t)kcol * 1024];

    for (int t = 0; t < Tq; ++t) {
        const int p = t & 1;
        float* zbuf = g_zT[p];
        float* znext = g_zT[p ^ 1];

        // ---------------- Phase A: h_att = h @ W_h_att -----------------------
        {   // stage full h (512 x 32 = 64KB) into dynsm
            const float4* src = (const float4*)zbuf;
#pragma unroll
            for (int ii = 0; ii < 16; ii++)
                ((float4*)dynsm)[tid + ii * NT] = src[tid + ii * NT];
            __syncthreads();
            const float* wr = &g_WhT[(size_t)(abase + aA) * Dq];
            float acc = 0.0f;
            int dbase = khA * 256;
            for (int d4 = 0; d4 < 64; d4++) {
                float4 w4 = *(const float4*)&wr[dbase + d4 * 4];
                int ds = (dbase + d4 * 4) * 32 + bA;
                acc = fmaf(w4.x, dynsm[ds], acc);
                acc = fmaf(w4.y, dynsm[ds + 32], acc);
                acc = fmaf(w4.z, dynsm[ds + 64], acc);
                acc = fmaf(w4.w, dynsm[ds + 96], acc);
            }
            s_ps[khA * 128 + bA * 4 + aA] = acc;
            __syncthreads();
            if (tid < 128) {
                float v = s_ps[tid] + s_ps[128 + tid];
                int b_ = tid >> 2, a_ = tid & 3;
                g_hatt[b_ * Dq + abase + a_] = v;
            }
        }
        bt += NB; grid_barrier(bt);

        // ---------------- Phase B: prj[b][l] ---------------------------------
        {
            if (tid < 128) {
                ((float4*)s_hs)[tid] = ((const float4*)&g_hatt[bb * Dq])[tid];
                ((float4*)s_ws)[tid] = ((const float4*)wprj)[tid];
            }
            __syncthreads();
            int l = lg + lloc;
            const float* ac = &g_attctx[((size_t)bb * Lq + l) * Dq + ach * 64];
            float acc = 0.0f;
            for (int q = 0; q < 16; q++) {
                float4 a4 = ((const float4*)ac)[q];
                int a0 = ach * 64 + q * 4;
                acc = fmaf(tanh_f(s_hs[a0 + 0] + a4.x), s_ws[a0 + 0], acc);
                acc = fmaf(tanh_f(s_hs[a0 + 1] + a4.y), s_ws[a0 + 1], acc);
                acc = fmaf(tanh_f(s_hs[a0 + 2] + a4.z), s_ws[a0 + 2], acc);
                acc = fmaf(tanh_f(s_hs[a0 + 3] + a4.w), s_ws[a0 + 3], acc);
            }
            s_ps[lloc * 8 + ach] = acc;
            __syncthreads();
            if (tid < 32) {
                float s = 0.0f;
#pragma unroll
                for (int q = 0; q < 8; q++) s += s_ps[tid * 8 + q];
                g_prj[bb * Lq + lg + tid] = s;
            }
        }
        bt += NB; grid_barrier(bt);

        // ---------------- Phase C: softmax + wctx ----------------------------
        {
            if (tid < 128) { s_pre[tid] = g_prj[bb * Lq + tid]; s_red[tid] = s_pre[tid]; }
            __syncthreads();
            for (int s = 64; s >= 1; s >>= 1) {
                if (tid < s) s_red[tid] = fmaxf(s_red[tid], s_red[tid + s]);
                __syncthreads();
            }
            float mx = s_red[0];
            __syncthreads();
            if (tid < 128) { s_al[tid] = __expf(s_pre[tid] - mx); s_red[tid] = s_al[tid]; }
            __syncthreads();
            for (int s = 64; s >= 1; s >>= 1) {
                if (tid < s) s_red[tid] += s_red[tid + s];
                __syncthreads();
            }
            float inv = __fdividef(1.0f, s_red[0]);
            __syncthreads();
            if (tid < 128) s_al[tid] *= inv;
            __syncthreads();
            int cc = cg + (tid & 127);
            int lh = tid >> 7;
            float acc = 0.0f;
            for (int l = lh * 64; l < lh * 64 + 64; l++)
                acc = fmaf(s_al[l], ctx[((size_t)bb * Lq + l) * Dq + cc], acc);
            s_ps[lh * 128 + (tid & 127)] = acc;
            __syncthreads();
            if (tid < 128) {
                float w = s_ps[tid] + s_ps[128 + tid];
                zbuf[(512 + cg + tid) * 32 + bb] = w;
            }
        }
        bt += NB; grid_barrier(bt);

        // ---------------- Phase D: gates + state update ----------------------
        {
            float a0 = 0.f, a1 = 0.f, a2 = 0.f, a3 = 0.f;
            for (int s = 0; s < 2; s++) {
                // stage zT[s*512 .. s*512+512) (64 KB)
                const float4* src = (const float4*)&zbuf[s * 512 * 32];
                __syncthreads();
#pragma unroll
                for (int ii = 0; ii < 16; ii++)
                    ((float4*)dynsm)[tid + ii * NT] = src[tid + ii * NT];
                __syncthreads();
                int dl0 = khD * 256;
                const float* wseg = &wrow[s * 512 + dl0];
                for (int d4 = 0; d4 < 64; d4++) {
                    float4 w4 = *(const float4*)&wseg[d4 * 4];
                    int zi = (dl0 + d4 * 4) * 32 + b0;
                    float4 z0 = *(const float4*)&dynsm[zi];
                    float4 z1 = *(const float4*)&dynsm[zi + 32];
                    float4 z2 = *(const float4*)&dynsm[zi + 64];
                    float4 z3 = *(const float4*)&dynsm[zi + 96];
                    a0 = fmaf(w4.x, z0.x, a0); a1 = fmaf(w4.x, z0.y, a1);
                    a2 = fmaf(w4.x, z0.z, a2); a3 = fmaf(w4.x, z0.w, a3);
                    a0 = fmaf(w4.y, z1.x, a0); a1 = fmaf(w4.y, z1.y, a1);
                    a2 = fmaf(w4.y, z1.z, a2); a3 = fmaf(w4.y, z1.w, a3);
                    a0 = fmaf(w4.z, z2.x, a0); a1 = fmaf(w4.z, z2.y, a1);
                    a2 = fmaf(w4.z, z2.z, a2); a3 = fmaf(w4.z, z2.w, a3);
                    a0 = fmaf(w4.w, z3.x, a0); a1 = fmaf(w4.w, z3.y, a1);
                    a2 = fmaf(w4.w, z3.z, a2); a3 = fmaf(w4.w, z3.w, a3);
                }
            }
            s_ps[khD * 512 + cD * 32 + b0 + 0] = a0;
            s_ps[khD * 512 + cD * 32 + b0 + 1] = a1;
            s_ps[khD * 512 + cD * 32 + b0 + 2] = a2;
            s_ps[khD * 512 + cD * 32 + b0 + 3] = a3;
            __syncthreads();
#pragma unroll
            for (int q = 0; q < 2; q++) {
                int o = tid + q * 256;
                int c_ = o >> 5, b_ = o & 31;
                int kk = (c_ >> 2) * 512 + jt * 4 + (c_ & 3);
                s_pre[o] = s_ps[o] + s_ps[512 + o] +
                           g_xW[((size_t)b_ * Tq + t) * K4 + kk];
            }
            __syncthreads();
            if (tid < 128) {
                int jj = tid >> 5, b_ = tid & 31;
                float si = sigmoid_f(s_pre[(0 * 4 + jj) * 32 + b_]);
                float sf = sigmoid_f(s_pre[(1 * 4 + jj) * 32 + b_]);
                float so = sigmoid_f(s_pre[(2 * 4 + jj) * 32 + b_]);
                float cd = tanh_f(s_pre[(3 * 4 + jj) * 32 + b_]);
                int j = jt * 4 + jj;
                int ci = j * 32 + b_;
                float cn = sf * g_c[ci] + si * cd;
                g_c[ci] = cn;
                float h = so * tanh_f(cn);
                znext[j * 32 + b_] = h;
                out[((size_t)b_ * Tq + t) * Dq + j] = h;
            }
        }
        bt += NB; grid_barrier(bt);
    }
}

// ------------- host ----------------------------------------------------------
extern "C" void kernel_launch(void* const* d_in, const int* in_sizes, int n_in,
                              void* d_out, int out_size) {
    const float* x    = (const float*)d_in[0];
    const float* ctx  = (const float*)d_in[1];
    const float* W    = (const float*)d_in[2];
    const float* V    = (const float*)d_in[3];
    const float* U    = (const float*)d_in[4];
    const float* b    = (const float*)d_in[5];
    const float* Wh   = (const float*)d_in[6];
    const float* Wc   = (const float*)d_in[7];
    const float* ba   = (const float*)d_in[8];
    const float* wprj = (const float*)d_in[9];
    float* out = (float*)d_out;

    static bool attr_done = false;
    if (!attr_done) {
        cudaFuncSetAttribute(k_recur, cudaFuncAttributeMaxDynamicSharedMemorySize, 65536);
        attr_done = true;
    }

    k_init<<<256, 256>>>(U, V, Wh);
    k_gemm_xw<<<dim3(16, 64), 256>>>(x, W, b);
    k_gemm_attctx<<<dim3(4, 32), 256>>>(ctx, Wc, ba);
    k_recur<<<NB, NT, 65536>>>(ctx, wprj, out);
}

// round 16
// speedup vs baseline: 1.7178x; 1.7178x over previous
#include <cuda_runtime.h>
#include <cstdint>

#define NB 128
#define NT 512
#define Bq 32
#define Tq 256
#define Dq 512
#define Lq 128
#define K4 2048

// ------------- device scratch (static globals: allowed) ---------------------
__device__ float g_xW[Bq * Tq * K4];        // 64 MB  x@W + b (native gate order)
__device__ float g_attctx[Bq * Lq * Dq];    // 8 MB   ctx@W_ctx_att + b_att
__device__ float g_UV[1024 * K4];           // 8 MB   [U;V] native [d][k]
__device__ float g_zT[2][1024 * Bq];        // ping-pong z = [h;wctx], layout [d][b]
__device__ float g_c[Dq * Bq];              // cell state [j][b]
__device__ float g_hatt[Bq * Dq];
__device__ float g_prj[Bq * Lq];
__device__ unsigned long long g_barcnt;

// ------------- math ----------------------------------------------------------
__device__ __forceinline__ float sigmoid_f(float x) {
    return __fdividef(1.0f, 1.0f + __expf(-x));
}
__device__ __forceinline__ float tanh_f(float x) {
    float e = __expf(2.0f * x);
    return 1.0f - __fdividef(2.0f, e + 1.0f);
}
__device__ __forceinline__ float tanh_fast(float x) {
    float y;
    asm("tanh.approx.f32 %0, %1;" : "=f"(y) : "f"(x));
    return y;
}

// ------------- grid barrier (monotonic counter) ------------------------------
__device__ __forceinline__ void grid_barrier(unsigned long long target) {
    __syncthreads();
    if (threadIdx.x == 0) {
        __threadfence();
        atomicAdd(&g_barcnt, 1ULL);
        volatile unsigned long long* c = &g_barcnt;
        while (*c < target) { __nanosleep(64); }
        __threadfence();
    }
    __syncthreads();
}

// ------------- init: UV copy + state zero ------------------------------------
__global__ void k_init(const float* __restrict__ U, const float* __restrict__ V) {
    int tid = blockIdx.x * blockDim.x + threadIdx.x;
    int n = blockDim.x * gridDim.x;
    if (tid == 0) g_barcnt = 0ULL;
    for (int i = tid; i < 2 * 1024 * Bq; i += n) g_zT[0][i] = 0.0f;   // both bufs
    for (int i = tid; i < Dq * Bq; i += n) g_c[i] = 0.0f;
    for (int i = tid; i < 1024 * K4; i += n) {
        int d = i >> 11, k = i & (K4 - 1);
        g_UV[i] = (d < Dq) ? U[(size_t)d * K4 + k] : V[(size_t)(d - Dq) * K4 + k];
    }
}

// ------------- 128x128x16 tiled SGEMM: C = A*B + bias ------------------------
__device__ __forceinline__ void gemm128_body(
    const float* __restrict__ A, const float* __restrict__ Bm,
    const float* __restrict__ bias, float* __restrict__ C,
    int M, int N, int K, float* As, float* Bs)
{
    const int tid = threadIdx.x;
    const int m0 = blockIdx.y * 128, n0 = blockIdx.x * 128;
    const int ty = tid >> 4, tx = tid & 15;
    const int arow = tid >> 2, acg = tid & 3;
    const int brow = tid >> 5, bcol = (tid & 31) * 4;

    float acc[8][8];
#pragma unroll
    for (int i = 0; i < 8; i++)
#pragma unroll
        for (int j = 0; j < 8; j++) acc[i][j] = 0.0f;

    for (int k0 = 0; k0 < K; k0 += 16) {
#pragma unroll
        for (int it = 0; it < 2; it++) {
            int r = arow + it * 64;
            float4 a4 = *(const float4*)&A[(size_t)(m0 + r) * K + k0 + acg * 4];
            As[(acg * 4 + 0) * 128 + r] = a4.x;
            As[(acg * 4 + 1) * 128 + r] = a4.y;
            As[(acg * 4 + 2) * 128 + r] = a4.z;
            As[(acg * 4 + 3) * 128 + r] = a4.w;
        }
#pragma unroll
        for (int it = 0; it < 2; it++) {
            int r = brow + it * 8;
            *(float4*)&Bs[r * 128 + bcol] =
                *(const float4*)&Bm[(size_t)(k0 + r) * N + n0 + bcol];
        }
        __syncthreads();
#pragma unroll
        for (int kk = 0; kk < 16; kk++) {
            float ar[8], br[8];
            *(float4*)&ar[0] = *(const float4*)&As[kk * 128 + ty * 8];
            *(float4*)&ar[4] = *(const float4*)&As[kk * 128 + ty * 8 + 4];
            *(float4*)&br[0] = *(const float4*)&Bs[kk * 128 + tx * 8];
            *(float4*)&br[4] = *(const float4*)&Bs[kk * 128 + tx * 8 + 4];
#pragma unroll
            for (int i = 0; i < 8; i++)
#pragma unroll
                for (int j = 0; j < 8; j++)
                    acc[i][j] = fmaf(ar[i], br[j], acc[i][j]);
        }
        __syncthreads();
    }
#pragma unroll
    for (int i = 0; i < 8; i++) {
        int row = m0 + ty * 8 + i;
#pragma unroll
        for (int j = 0; j < 8; j++) {
            int col = n0 + tx * 8 + j;
            C[(size_t)row * N + col] = acc[i][j] + bias[col];
        }
    }
}

__global__ void __launch_bounds__(256) k_gemm_xw(
    const float* __restrict__ x, const float* __restrict__ W,
    const float* __restrict__ b) {
    __shared__ __align__(16) float As[16 * 128];
    __shared__ __align__(16) float Bs[16 * 128];
    gemm128_body(x, W, b, g_xW, Bq * Tq, K4, Dq, As, Bs);
}
__global__ void __launch_bounds__(256) k_gemm_attctx(
    const float* __restrict__ ctx, const float* __restrict__ Wc,
    const float* __restrict__ ba) {
    __shared__ __align__(16) float As[16 * 128];
    __shared__ __align__(16) float Bs[16 * 128];
    gemm128_body(ctx, Wc, ba, g_attctx, Bq * Lq, Dq, Dq, As, Bs);
}

// ------------- persistent recurrence -----------------------------------------
extern __shared__ float dynsm[];   // 64 KB: z staging / partial-sum scratch

__global__ void __launch_bounds__(NT, 1) k_recur(
    const float* __restrict__ ctx,      // (B, L, D)
    const float* __restrict__ Wh,       // (D_OUT, A_HID) native [d][a]
    const float* __restrict__ wprj,     // (A_HID,)
    float* __restrict__ out)            // (B, T, D)
{
    __shared__ float s_hs[512];
    __shared__ float s_ws[512];
    __shared__ float s_ps[512];
    __shared__ float s_pre[512];
    __shared__ float s_al[128];
    __shared__ float s_red[128];

    const int tid = threadIdx.x;
    const int blk = blockIdx.x;
    unsigned long long bt = 0;

    // ---- phase A coords: a-tile of 4, per-thread 4a x 4b, 64-way d-split ----
    const int abase = blk * 4;
    const int bgA = tid & 7, b0A = bgA * 4;
    const int dsA = tid >> 3;                 // 0..63 -> 8 d each
    // ---- phase B coords ----
    const int bb = blk >> 2;
    const int lg = (blk & 3) * 32;
    const int lloc = tid >> 4;                // 0..31
    const int ach = tid & 15;                 // 32 a each
    // ---- phase C coords ----
    const int cg = (blk & 3) * 128;
    // ---- phase D coords: 16 cols/CTA, per-thread 4col x 4b, 16-way d-split --
    const int jt = blk;
    const int bgD = tid & 7, b0D = bgD * 4;
    const int cg4 = (tid >> 3) & 3;           // gate index (col group)
    const int k0 = cg4 * 512 + jt * 4;        // 4 contiguous k columns
    const int dsD = tid >> 5;                 // 0..15 -> 32 d per half
    const int dl0 = dsD * 32;

    for (int t = 0; t < Tq; ++t) {
        const int p = t & 1;
        float* zbuf = g_zT[p];
        float* znext = g_zT[p ^ 1];

        // ---------------- Phase A: h_att = h @ W_h_att -----------------------
        {
            float acc[4][4];
#pragma unroll
            for (int i = 0; i < 4; i++)
#pragma unroll
                for (int j = 0; j < 4; j++) acc[i][j] = 0.0f;
            const float* whb = &Wh[(size_t)(dsA * 8) * Dq + abase];
            const float* zb = &zbuf[(dsA * 8) * 32 + b0A];
#pragma unroll
            for (int q = 0; q < 8; q++) {
                float4 w4 = *(const float4*)&whb[q * Dq];
                float4 z4 = *(const float4*)&zb[q * 32];
                acc[0][0] = fmaf(w4.x, z4.x, acc[0][0]); acc[0][1] = fmaf(w4.x, z4.y, acc[0][1]);
                acc[0][2] = fmaf(w4.x, z4.z, acc[0][2]); acc[0][3] = fmaf(w4.x, z4.w, acc[0][3]);
                acc[1][0] = fmaf(w4.y, z4.x, acc[1][0]); acc[1][1] = fmaf(w4.y, z4.y, acc[1][1]);
                acc[1][2] = fmaf(w4.y, z4.z, acc[1][2]); acc[1][3] = fmaf(w4.y, z4.w, acc[1][3]);
                acc[2][0] = fmaf(w4.z, z4.x, acc[2][0]); acc[2][1] = fmaf(w4.z, z4.y, acc[2][1]);
                acc[2][2] = fmaf(w4.z, z4.z, acc[2][2]); acc[2][3] = fmaf(w4.z, z4.w, acc[2][3]);
                acc[3][0] = fmaf(w4.w, z4.x, acc[3][0]); acc[3][1] = fmaf(w4.w, z4.y, acc[3][1]);
                acc[3][2] = fmaf(w4.w, z4.z, acc[3][2]); acc[3][3] = fmaf(w4.w, z4.w, acc[3][3]);
            }
#pragma unroll
            for (int aa = 0; aa < 4; aa++)
                *(float4*)&dynsm[dsA * 128 + aa * 32 + b0A] =
                    make_float4(acc[aa][0], acc[aa][1], acc[aa][2], acc[aa][3]);
            __syncthreads();
            if (tid < 128) {
                float s = 0.0f;
#pragma unroll
                for (int r = 0; r < 64; r++) s += dynsm[r * 128 + tid];
                int aa = tid >> 5, b_ = tid & 31;
                g_hatt[b_ * Dq + abase + aa] = s;
            }
        }
        bt += NB; grid_barrier(bt);

        // ---------------- Phase B: prj[b][l] ---------------------------------
        {
            if (tid < 128) {
                ((float4*)s_hs)[tid] = ((const float4*)&g_hatt[bb * Dq])[tid];
                ((float4*)s_ws)[tid] = ((const float4*)wprj)[tid];
            }
            __syncthreads();
            const float* ac = &g_attctx[((size_t)bb * Lq + lg + lloc) * Dq + ach * 32];
            float acc = 0.0f;
#pragma unroll
            for (int q = 0; q < 8; q++) {
                float4 a4 = ((const float4*)ac)[q];
                int a0 = ach * 32 + q * 4;
                acc = fmaf(tanh_fast(s_hs[a0 + 0] + a4.x), s_ws[a0 + 0], acc);
                acc = fmaf(tanh_fast(s_hs[a0 + 1] + a4.y), s_ws[a0 + 1], acc);
                acc = fmaf(tanh_fast(s_hs[a0 + 2] + a4.z), s_ws[a0 + 2], acc);
                acc = fmaf(tanh_fast(s_hs[a0 + 3] + a4.w), s_ws[a0 + 3], acc);
            }
            s_ps[lloc * 16 + ach] = acc;
            __syncthreads();
            if (tid < 32) {
                float s = 0.0f;
#pragma unroll
                for (int q = 0; q < 16; q++) s += s_ps[tid * 16 + q];
                g_prj[bb * Lq + lg + tid] = s;
            }
        }
        bt += NB; grid_barrier(bt);

        // ---------------- Phase C: softmax + wctx ----------------------------
        {
            if (tid < 128) {
                float v = g_prj[bb * Lq + tid];
                s_pre[tid] = v; s_red[tid] = v;
            }
            __syncthreads();
            for (int s = 64; s >= 1; s >>= 1) {
                if (tid < s) s_red[tid] = fmaxf(s_red[tid], s_red[tid + s]);
                __syncthreads();
            }
            float mx = s_red[0];
            __syncthreads();
            if (tid < 128) { s_al[tid] = __expf(s_pre[tid] - mx); s_red[tid] = s_al[tid]; }
            __syncthreads();
            for (int s = 64; s >= 1; s >>= 1) {
                if (tid < s) s_red[tid] += s_red[tid + s];
                __syncthreads();
            }
            float inv = __fdividef(1.0f, s_red[0]);
            __syncthreads();
            if (tid < 128) s_al[tid] *= inv;
            __syncthreads();
            int ccx = cg + (tid & 127);
            int lh = tid >> 7;                 // 0..3, 32 l each
            float acc = 0.0f;
#pragma unroll 4
            for (int l = lh * 32; l < lh * 32 + 32; l++)
                acc = fmaf(s_al[l], ctx[((size_t)bb * Lq + l) * Dq + ccx], acc);
            s_ps[lh * 128 + (tid & 127)] = acc;
            __syncthreads();
            if (tid < 128) {
                float w = s_ps[tid] + s_ps[128 + tid] + s_ps[256 + tid] + s_ps[384 + tid];
                zbuf[(512 + cg + tid) * 32 + bb] = w;
            }
        }
        bt += NB; grid_barrier(bt);

        // ---------------- Phase D: gate GEMM + state update ------------------
        {
            float acc[4][4];
#pragma unroll
            for (int i = 0; i < 4; i++)
#pragma unroll
                for (int j = 0; j < 4; j++) acc[i][j] = 0.0f;

            for (int s = 0; s < 2; s++) {
                __syncthreads();
                const float4* src = (const float4*)&zbuf[s * 512 * 32];
                float4* dst = (float4*)dynsm;
#pragma unroll
                for (int i = 0; i < 8; i++)
                    dst[tid + i * NT] = src[tid + i * NT];
                __syncthreads();
                const float* wbase = &g_UV[(size_t)(s * 512 + dl0) * K4 + k0];
                const float* zsm = &dynsm[dl0 * 32 + b0D];
#pragma unroll 4
                for (int q = 0; q < 32; q++) {
                    float4 w4 = *(const float4*)&wbase[(size_t)q * K4];
                    float4 z4 = *(const float4*)&zsm[q * 32];
                    acc[0][0] = fmaf(w4.x, z4.x, acc[0][0]); acc[0][1] = fmaf(w4.x, z4.y, acc[0][1]);
                    acc[0][2] = fmaf(w4.x, z4.z, acc[0][2]); acc[0][3] = fmaf(w4.x, z4.w, acc[0][3]);
                    acc[1][0] = fmaf(w4.y, z4.x, acc[1][0]); acc[1][1] = fmaf(w4.y, z4.y, acc[1][1]);
                    acc[1][2] = fmaf(w4.y, z4.z, acc[1][2]); acc[1][3] = fmaf(w4.y, z4.w, acc[1][3]);
                    acc[2][0] = fmaf(w4.z, z4.x, acc[2][0]); acc[2][1] = fmaf(w4.z, z4.y, acc[2][1]);
                    acc[2][2] = fmaf(w4.z, z4.z, acc[2][2]); acc[2][3] = fmaf(w4.z, z4.w, acc[2][3]);
                    acc[3][0] = fmaf(w4.w, z4.x, acc[3][0]); acc[3][1] = fmaf(w4.w, z4.y, acc[3][1]);
                    acc[3][2] = fmaf(w4.w, z4.z, acc[3][2]); acc[3][3] = fmaf(w4.w, z4.w, acc[3][3]);
                }
            }
            __syncthreads();   // all reads of staged z done before scratch reuse
#pragma unroll
            for (int jj = 0; jj < 4; jj++)
                *(float4*)&dynsm[dsD * 512 + (cg4 * 4 + jj) * 32 + b0D] =
                    make_float4(acc[jj][0], acc[jj][1], acc[jj][2], acc[jj][3]);
            __syncthreads();
            {
                float sum = 0.0f;
#pragma unroll
                for (int r = 0; r < 16; r++) sum += dynsm[r * 512 + tid];
                int cc = tid >> 5, bo = tid & 31;
                int g = cc >> 2, jj = cc & 3;
                s_pre[tid] = sum + g_xW[((size_t)bo * Tq + t) * K4 + g * 512 + jt * 4 + jj];
            }
            __syncthreads();
            if (tid < 128) {
                int jj = tid >> 5, b_ = tid & 31;
                float vi = sigmoid_f(s_pre[(0 * 4 + jj) * 32 + b_]);
                float vf = sigmoid_f(s_pre[(1 * 4 + jj) * 32 + b_]);
                float vo = sigmoid_f(s_pre[(2 * 4 + jj) * 32 + b_]);
                float cd = tanh_f(s_pre[(3 * 4 + jj) * 32 + b_]);
                int j = jt * 4 + jj;
                int ci = j * 32 + b_;
                float cn = vf * g_c[ci] + vi * cd;
                g_c[ci] = cn;
                float h = vo * tanh_f(cn);
                znext[j * 32 + b_] = h;
                out[((size_t)b_ * Tq + t) * Dq + j] = h;
            }
        }
        bt += NB; grid_barrier(bt);
    }
}

// ------------- host ----------------------------------------------------------
extern "C" void kernel_launch(void* const* d_in, const int* in_sizes, int n_in,
                              void* d_out, int out_size) {
    const float* x    = (const float*)d_in[0];
    const float* ctx  = (const float*)d_in[1];
    const float* W    = (const float*)d_in[2];
    const float* V    = (const float*)d_in[3];
    const float* U    = (const float*)d_in[4];
    const float* b    = (const float*)d_in[5];
    const float* Wh   = (const float*)d_in[6];
    const float* Wc   = (const float*)d_in[7];
    const float* ba   = (const float*)d_in[8];
    const float* wprj = (const float*)d_in[9];
    float* out = (float*)d_out;

    static bool attr_done = false;
    if (!attr_done) {
        cudaFuncSetAttribute(k_recur, cudaFuncAttributeMaxDynamicSharedMemorySize, 65536);
        attr_done = true;
    }

    k_init<<<256, 256>>>(U, V);
    k_gemm_xw<<<dim3(16, 64), 256>>>(x, W, b);
    k_gemm_attctx<<<dim3(4, 32), 256>>>(ctx, Wc, ba);
    k_recur<<<NB, NT, 65536>>>(ctx, Wh, wprj, out);
}